// round 7
// baseline (speedup 1.0000x reference)
#include <cuda_runtime.h>
#include <cuda_bf16.h>
#include <cstdint>

// out[r][c] = in[2r+1][2c+1], in: 8192x8192 fp32, out: 4096x4096 fp32.
// R2/R5 shape: one block per output row, 2x LDG.128 per output float4,
// loads front-batched (MLP=8).
// L2 policy via createpolicy + cache_hint (128-bit-compatible form):
//   reads  evict_first (128MB pure stream, minimal L2 footprint)
//   writes evict_last  (64MB output pinned in ~126MB L2 across replays)

#define N_IN   8192
#define N_OUT  4096
#define F4_ROW (N_OUT / 4)   // 1024 output float4s per row
#define TPB    256
#define UNROLL 4             // F4_ROW / TPB

__device__ __forceinline__ float4 ldg128_ef(const float4* p, uint64_t pol) {
    float4 r;
    asm volatile("ld.global.nc.L2::cache_hint.v4.f32 {%0,%1,%2,%3}, [%4], %5;"
                 : "=f"(r.x), "=f"(r.y), "=f"(r.z), "=f"(r.w)
                 : "l"(p), "l"(pol));
    return r;
}

__device__ __forceinline__ void stg128_el(float4* p, float4 v, uint64_t pol) {
    asm volatile("st.global.L2::cache_hint.v4.f32 [%0], {%1,%2,%3,%4}, %5;"
                 :: "l"(p), "f"(v.x), "f"(v.y), "f"(v.z), "f"(v.w), "l"(pol)
                 : "memory");
}

__global__ __launch_bounds__(TPB) void decimate2_kernel(
    const float4* __restrict__ in, float4* __restrict__ out)
{
    uint64_t pol_ef, pol_el;
    asm("createpolicy.fractional.L2::evict_first.b64 %0, 1.0;" : "=l"(pol_ef));
    asm("createpolicy.fractional.L2::evict_last.b64 %0, 1.0;"  : "=l"(pol_el));

    const int orow = blockIdx.x;
    const int tid  = threadIdx.x;

    const float4* in_row  = in  + (size_t)(2 * orow + 1) * (N_IN / 4);
    float4*       out_row = out + (size_t)orow * F4_ROW;

    float4 a[UNROLL], b[UNROLL];

    // Front-batched loads: 8 independent LDG.128 in flight per thread.
#pragma unroll
    for (int k = 0; k < UNROLL; k++) {
        const int oc4 = tid + k * TPB;
        a[k] = ldg128_ef(&in_row[2 * oc4],     pol_ef);
        b[k] = ldg128_ef(&in_row[2 * oc4 + 1], pol_ef);
    }

#pragma unroll
    for (int k = 0; k < UNROLL; k++) {
        const int oc4 = tid + k * TPB;
        float4 r;
        r.x = a[k].y;   // odd col 8*oc4+1
        r.y = a[k].w;   // odd col 8*oc4+3
        r.z = b[k].y;   // odd col 8*oc4+5
        r.w = b[k].w;   // odd col 8*oc4+7
        stg128_el(&out_row[oc4], r, pol_el);
    }
}

extern "C" void kernel_launch(void* const* d_in, const int* in_sizes, int n_in,
                              void* d_out, int out_size)
{
    const float4* in  = (const float4*)d_in[0];
    float4*       out = (float4*)d_out;

    decimate2_kernel<<<N_OUT, TPB>>>(in, out);
}